// round 17
// baseline (speedup 1.0000x reference)
#include <cuda_runtime.h>
#include <cuda_fp16.h>
#include <math.h>
#include <cstdint>

#define HD 2048
#define ID 1408
#define NE 16
#define TK 4
#define NT 1024
#define SID 2816
#define RSCALE 2.5f

// ---------------- scratch ----------------
__device__ int    d_cnt[NE];
__device__ int    d_tok[NE * NT];
__device__ float  d_wt [NE * NT];
__device__ __half w_g16[NE * ID * HD];
__device__ __half w_u16[NE * ID * HD];
__device__ __half w_d16[NE * HD * ID];
__device__ __half sw_g16[SID * HD];
__device__ __half sw_u16[SID * HD];
__device__ __half sw_d16[HD * SID];
__device__ __half x16  [NT * HD];
__device__ __half h_r16[NE * NT * ID];
__device__ __half h_s16[NT * SID];

// ---------------- PTX helpers ----------------
__device__ __forceinline__ uint32_t smem_u32(const void* p) {
    uint32_t a;
    asm("{ .reg .u64 t; cvta.to.shared.u64 t, %1; cvt.u32.u64 %0, t; }"
        : "=r"(a) : "l"(p));
    return a;
}
#define CP_ASYNC(dst, src, sz) \
    asm volatile("cp.async.cg.shared.global [%0], [%1], 16, %2;" \
                 :: "r"(dst), "l"(src), "r"(sz) : "memory")
#define CP_COMMIT() asm volatile("cp.async.commit_group;" ::: "memory")
#define CP_WAIT(n)  asm volatile("cp.async.wait_group %0;" :: "n"(n) : "memory")

__device__ __forceinline__ void mma16(float* c, const uint32_t* a, const uint32_t* b) {
    asm volatile(
        "mma.sync.aligned.m16n8k16.row.col.f32.f16.f16.f32 "
        "{%0,%1,%2,%3}, {%4,%5,%6,%7}, {%8,%9}, {%0,%1,%2,%3};"
        : "+f"(c[0]), "+f"(c[1]), "+f"(c[2]), "+f"(c[3])
        : "r"(a[0]), "r"(a[1]), "r"(a[2]), "r"(a[3]), "r"(b[0]), "r"(b[1]));
}
__device__ __forceinline__ void red_add2(float* o, float v0, float v1) {
    asm volatile("red.global.add.v2.f32 [%0], {%1, %2};"
                 :: "l"(o), "f"(v0), "f"(v1) : "memory");
}
__device__ __forceinline__ float silu(float g) { return g / (1.f + __expf(-g)); }
__device__ __forceinline__ uint32_t h2u(__half2 h) {
    uint32_t u; *(__half2*)&u = h; return u;
}
__device__ __forceinline__ uint32_t pk(float a, float b) {
    return h2u(__floats2half2_rn(a, b));
}

#define ROWB 96
#define ROWU2 12

// ---------------- init ----------------
__global__ void init_kernel() {
    if (threadIdx.x < NE) d_cnt[threadIdx.x] = 0;
}

// ---------------- conversion unit (pair-permuted fp16) ----------------------
#define U_W ((size_t)NE * ID * HD / 16)
#define U_S ((size_t)SID * HD / 16)
#define U_X ((size_t)NT * HD / 16)
#define U_PRO (2 * U_W + 3 * U_S + U_X)
#define CONV_BLOCKS ((int)(U_PRO / 256))
#define ZERO_BLOCKS ((NT * HD) / 1024)
#define PRO_BLOCKS  (NT + ZERO_BLOCKS + CONV_BLOCKS)
#define WD_ZSLICES  ((int)(U_W / 512 / 88))     // 64 z-slices of 22x4 CTAs @512thr

__device__ __forceinline__ void conv_unit(const float4* __restrict__ s,
                                          uint4* __restrict__ d, size_t t) {
    float4 f0 = s[4 * t], f1 = s[4 * t + 1], f2 = s[4 * t + 2], f3 = s[4 * t + 3];
    d[2 * t]     = make_uint4(pk(f0.x, f0.y), pk(f2.x, f2.y),
                              pk(f0.z, f0.w), pk(f2.z, f2.w));
    d[2 * t + 1] = make_uint4(pk(f1.x, f1.y), pk(f3.x, f3.y),
                              pk(f1.z, f1.w), pk(f3.z, f3.w));
}

// ---------------- fused prologue (256 thr): gate | zero | conv -------------
__device__ void gate_block(int t, const float* __restrict__ x,
                           const float* __restrict__ gw,
                           const float* __restrict__ gb) {
    __shared__ float s_sc[NE];
    const int wid = threadIdx.x >> 5, lane = threadIdx.x & 31;
    const float4* xr = (const float4*)(x + (size_t)t * HD);
    #pragma unroll
    for (int eo = 0; eo < 2; eo++) {
        const int e = wid + eo * 8;
        const float4* wr = (const float4*)(gw + (size_t)e * HD);
        float acc = 0.f;
        #pragma unroll 4
        for (int k = lane; k < HD / 4; k += 32) {
            float4 a = xr[k], b = wr[k];
            acc += a.x * b.x + a.y * b.y + a.z * b.z + a.w * b.w;
        }
        #pragma unroll
        for (int o = 16; o; o >>= 1) acc += __shfl_xor_sync(0xffffffffu, acc, o);
        if (lane == 0) s_sc[e] = 1.f / (1.f + expf(-acc)) + gb[e];
    }
    __syncthreads();
    if (threadIdx.x != 0) return;

    float sc[NE];
    #pragma unroll
    for (int e = 0; e < NE; e++) sc[e] = s_sc[e];
    float gs[4];
    #pragma unroll
    for (int g = 0; g < 4; g++) {
        float m = sc[g * 4];
        #pragma unroll
        for (int j = 1; j < 4; j++) m = fmaxf(m, sc[g * 4 + j]);
        gs[g] = m;
    }
    int g0 = 0;
    for (int g = 1; g < 4; g++) if (gs[g] > gs[g0]) g0 = g;
    int g1 = -1;
    for (int g = 0; g < 4; g++) {
        if (g == g0) continue;
        if (g1 < 0 || gs[g] > gs[g1]) g1 = g;
    }
    float masked[NE];
    #pragma unroll
    for (int e = 0; e < NE; e++) {
        int g = e >> 2;
        masked[e] = (g == g0 || g == g1) ? sc[e] : 0.f;
    }
    int idx[TK]; float w[TK]; bool used[NE];
    #pragma unroll
    for (int e = 0; e < NE; e++) used[e] = false;
    float wsum = 0.f;
    for (int k = 0; k < TK; k++) {
        int best = -1;
        for (int e = 0; e < NE; e++) {
            if (used[e]) continue;
            if (best < 0 || masked[e] > masked[best]) best = e;
        }
        used[best] = true;
        idx[k] = best; w[k] = masked[best]; wsum += masked[best];
    }
    const float inv = 1.f / (wsum + 1e-6f);
    for (int k = 0; k < TK; k++) {
        int e = idx[k];
        int pos = atomicAdd(&d_cnt[e], 1);
        d_tok[e * NT + pos] = t;
        d_wt [e * NT + pos] = w[k] * inv * RSCALE;
    }
}

__global__ void prologue(const float* x, const float* gate_w, const float* gate_b,
                         float4* out,
                         const float4* wg, const float4* wu,
                         const float4* sg, const float4* su, const float4* sd,
                         uint4* owg, uint4* owu,
                         uint4* osg, uint4* osu, uint4* osd, uint4* oxx) {
    const int b = blockIdx.x;
    if (b < NT) { gate_block(b, x, gate_w, gate_b); return; }
    if (b < NT + ZERO_BLOCKS) {
        out[(size_t)(b - NT) * 256 + threadIdx.x] = make_float4(0.f, 0.f, 0.f, 0.f);
        return;
    }
    size_t u = (size_t)(b - NT - ZERO_BLOCKS) * 256 + threadIdx.x;
    if (u < U_W) { conv_unit(wg, owg, u); return; }
    u -= U_W;
    if (u < U_W) { conv_unit(wu, owu, u); return; }
    u -= U_W;
    if (u < U_S) { conv_unit(sg, osg, u); return; }
    u -= U_S;
    if (u < U_S) { conv_unit(su, osu, u); return; }
    u -= U_S;
    if (u < U_S) { conv_unit(sd, osd, u); return; }
    u -= U_S;
    conv_unit((const float4*)x, oxx, u);
}

// ---------------- GEMM1: 256M x 64N dual, 512 thr, 4-stage -----------------
// z 0..15 routed, z 16/17 shared halves, z>=18 wd-conv fill.
// Stage 36864B: A 256x96 @0 | G 64x96 @24576 | U 64x96 @30720
#define G1_STAGE 36864
#define G1_SMEM  (1024 + 4 * G1_STAGE)
__global__ void __launch_bounds__(512, 1)
gemm1_h(const __half* __restrict__ X,
        const __half* __restrict__ Wg_r, const __half* __restrict__ Wu_r,
        const __half* __restrict__ Wg_s, const __half* __restrict__ Wu_s,
        __half* __restrict__ Hr, __half* __restrict__ Hs,
        const float4* __restrict__ Wd32, uint4* __restrict__ oWd) {
    const int e = blockIdx.z;
    if (e >= NE + 2) {
        const size_t cid = ((size_t)(e - NE - 2) * 4 + blockIdx.y) * 22 + blockIdx.x;
        conv_unit(Wd32, oWd, cid * 512 + threadIdx.x);
        return;
    }
    const bool SH = (e >= NE);
    int M, ldH, n0;
    const __half *Wg, *Wu; __half* Ho;
    if (SH) {
        M = NT; ldH = SID;
        Wg = Wg_s; Wu = Wu_s; Ho = Hs;
        n0 = ((int)blockIdx.x + (e == NE + 1 ? 22 : 0)) * 64;
    } else {
        M = d_cnt[e]; ldH = ID;
        Wg = Wg_r + (size_t)e * ID * HD;
        Wu = Wu_r + (size_t)e * ID * HD;
        Ho = Hr + (size_t)e * NT * ID;
        n0 = (int)blockIdx.x * 64;
    }
    const int m0 = blockIdx.y * 256;
    if (m0 >= M) return;
    const int K = HD;

    extern __shared__ char smem[];
    int* s_tok = (int*)smem;
    const int tid = threadIdx.x, lane = tid & 31, wid = tid >> 5;
    const int wr = wid >> 2, wc = wid & 3;
    if (!SH && tid < 256) s_tok[tid] = (m0 + tid < M) ? d_tok[e * NT + m0 + tid] : 0;
    __syncthreads();

    // loader: tid<256 -> A row tid (4x16B); 256-383 G; 384-511 U (2x16B each)
    const uint32_t sb = smem_u32(smem) + 1024;
    const char* Lp;
    uint32_t dL;
    int nseg;
    uint32_t szL = 16u;
    if (tid < 256) {
        const bool aok = (m0 + tid) < M;
        const int ar = SH ? (aok ? m0 + tid : 0) : (aok ? s_tok[tid] : 0);
        Lp = (const char*)(X + (size_t)ar * K);
        dL = sb + tid * ROWB;
        nseg = 4;
        szL = aok ? 16u : 0u;
    } else if (tid < 384) {
        const int tw = tid - 256, rW = tw >> 1, h = tw & 1;
        Lp = (const char*)(Wg + (size_t)(n0 + rW) * K) + h * 32;
        dL = sb + 24576 + rW * ROWB + h * 32;
        nseg = 2;
    } else {
        const int tw = tid - 384, rW = tw >> 1, h = tw & 1;
        Lp = (const char*)(Wu + (size_t)(n0 + rW) * K) + h * 32;
        dL = sb + 30720 + rW * ROWB + h * 32;
        nseg = 2;
    }

    const int C = K >> 5;
    auto load = [&](int c, int buf) {
        const char* s = Lp + c * 64;
        const uint32_t d = dL + buf * G1_STAGE;
        CP_ASYNC(d,      s,      szL);
        CP_ASYNC(d + 16, s + 16, szL);
        if (nseg == 4) {
            CP_ASYNC(d + 32, s + 32, szL);
            CP_ASYNC(d + 48, s + 48, szL);
        }
    };

    float cg[4][2][4] = {}, cu[4][2][4] = {};
    #pragma unroll
    for (int s = 0; s < 3; s++) { if (s < C) load(s, s); CP_COMMIT(); }

    const int l4 = lane >> 2, lm = lane & 3;
    const int a_off = (wr * 64 + l4) * ROWU2 + lm;
    const int g_off = 3072 + (wc * 16 + l4) * ROWU2 + lm;   // 24576B/8
    #pragma unroll 1
    for (int c = 0; c < C; c++) {
        CP_WAIT(2);
        __syncthreads();
        const int nc = c + 3;
        if (nc < C) load(nc, nc & 3);
        CP_COMMIT();
        const uint2* S = (const uint2*)(smem + 1024 + (c & 3) * G1_STAGE);
        #pragma unroll
        for (int ks = 0; ks < 2; ks++) {
            uint32_t a[4][4];
            #pragma unroll
            for (int mi = 0; mi < 4; mi++) {
                const uint2 p = S[a_off + mi * (16 * ROWU2) + ks * 4];
                const uint2 q = S[a_off + mi * (16 * ROWU2) + 8 * ROWU2 + ks * 4];
                a[mi][0] = p.x; a[mi][1] = q.x; a[mi][2] = p.y; a[mi][3] = q.y;
            }
            #pragma unroll
            for (int ni = 0; ni < 2; ni++) {
                const uint2 vg = S[g_off + ni * (8 * ROWU2) + ks * 4];
                const uint2 vu = S[g_off + 768 + ni * (8 * ROWU2) + ks * 4];
                uint32_t bg[2] = { vg.x, vg.y };
                uint32_t bu[2] = { vu.x, vu.y };
                #pragma unroll
                for (int mi = 0; mi < 4; mi++) {
                    mma16(cg[mi][ni], a[mi], bg);
                    mma16(cu[mi][ni], a[mi], bu);
                }
            }
        }
    }
    #pragma unroll
    for (int mi = 0; mi < 4; mi++)
        #pragma unroll
        for (int h = 0; h < 2; h++) {
            const int r = m0 + wr * 64 + mi * 16 + l4 + h * 8;
            if (r >= M) continue;
            const float v0 = silu(cg[mi][0][2 * h + 0]) * cu[mi][0][2 * h + 0];
            const float v1 = silu(cg[mi][0][2 * h + 1]) * cu[mi][0][2 * h + 1];
            const float v2 = silu(cg[mi][1][2 * h + 0]) * cu[mi][1][2 * h + 0];
            const float v3 = silu(cg[mi][1][2 * h + 1]) * cu[mi][1][2 * h + 1];
            uint2 val = { pk(v0, v1), pk(v2, v3) };
            ((uint2*)(Ho + (size_t)r * ldH + n0 + wc * 16))[lm] = val;
        }
}

// ---------------- GEMM2: 256M x 64N, 512 thr, 4-stage ----------------------
// z=0 shared (K=SID), z=1..16 routed e=z-1.
// Stage 30720B: A 256x96 @0 | B 64x96 @24576
#define G2_STAGE 30720
#define G2_SMEM  (2048 + 4 * G2_STAGE)
__global__ void __launch_bounds__(512, 1)
gemm2_h(const __half* __restrict__ Hr, const __half* __restrict__ Wd_r,
        const __half* __restrict__ Hs, const __half* __restrict__ Wd_s,
        float* __restrict__ Out) {
    const int zz = blockIdx.z;
    const bool SH = (zz == 0);
    const int e = SH ? 0 : zz - 1;
    int M, K;
    const __half *Hin, *Wd;
    if (SH) {
        M = NT; K = SID; Hin = Hs; Wd = Wd_s;
    } else {
        M = d_cnt[e]; K = ID;
        Hin = Hr + (size_t)e * NT * ID;
        Wd  = Wd_r + (size_t)e * HD * ID;
    }
    const int m0 = blockIdx.y * 256;
    if (m0 >= M) return;
    const int n0 = blockIdx.x * 64;

    extern __shared__ char smem[];
    int*   s_tok = (int*)smem;
    float* s_wt  = (float*)(smem + 1024);
    const int tid = threadIdx.x, lane = tid & 31, wid = tid >> 5;
    const int wr = wid >> 2, wc = wid & 3;
    if (tid < 256) {
        const bool ok = m0 + tid < M;
        if (SH) { s_tok[tid] = ok ? m0 + tid : 0; s_wt[tid] = 1.f; }
        else {
            s_tok[tid] = ok ? d_tok[e * NT + m0 + tid] : 0;
            s_wt [tid] = ok ? d_wt [e * NT + m0 + tid] : 0.f;
        }
    }
    __syncthreads();

    const uint32_t sb = smem_u32(smem) + 2048;
    const char* Lp;
    uint32_t dL;
    int nseg;
    uint32_t szL = 16u;
    if (tid < 256) {
        const bool aok = (m0 + tid) < M;
        Lp = (const char*)(Hin + (size_t)(aok ? m0 + tid : 0) * K);
        dL = sb + tid * ROWB;
        nseg = 4;
        szL = aok ? 16u : 0u;
    } else {
        const int tw = tid - 256, rB = tw >> 2, sg = tw & 3;
        Lp = (const char*)(Wd + (size_t)(n0 + rB) * K) + sg * 16;
        dL = sb + 24576 + rB * ROWB + sg * 16;
        nseg = 1;
    }

    const int C = K >> 5;
    auto load = [&](int c, int buf) {
        const char* s = Lp + c * 64;
        const uint32_t d = dL + buf * G2_STAGE;
        CP_ASYNC(d, s, szL);
        if (nseg == 4) {
            CP_ASYNC(d + 16, s + 16, szL);
            CP_ASYNC(d + 32, s + 32, szL);
            CP_ASYNC(d + 48, s + 48, szL);
        }
    };

    float acc[4][2][4] = {};
    #pragma unroll
    for (int s = 0; s < 3; s++) { if (s < C) load(s, s); CP_COMMIT(); }

    const int l4 = lane >> 2, lm = lane & 3;
    const int a_off = (wr * 64 + l4) * ROWU2 + lm;
    const int b_off = 3072 + (wc * 16 + l4) * ROWU2 + lm;
    #pragma unroll 1
    for (int c = 0; c < C; c++) {
        CP_WAIT(2);
        __syncthreads();
        const int nc = c + 3;
        if (nc < C) load(nc, nc & 3);
        CP_COMMIT();
        const uint2* S = (const uint2*)(smem + 2048 + (c & 3) * G2_STAGE);
        #pragma unroll
        for (int ks = 0; ks < 2; ks++) {
            uint32_t a[4][4];
            #pragma unroll
            for (int mi = 0; mi < 4; mi++) {
                const uint2 p = S[a_off + mi * (16 * ROWU2) + ks * 4];
                const uint2 q = S[a_off + mi * (16 * ROWU2) + 8 * ROWU2 + ks * 4];
                a[mi][0] = p.x; a[mi][1] = q.x; a[mi][2] = p.y; a[mi][3] = q.y;
            }
            #pragma unroll
            for (int ni = 0; ni < 2; ni++) {
                const uint2 vb = S[b_off + ni * (8 * ROWU2) + ks * 4];
                uint32_t b[2] = { vb.x, vb.y };
                #pragma unroll
                for (int mi = 0; mi < 4; mi++)
                    mma16(acc[mi][ni], a[mi], b);
            }
        }
    }
    #pragma unroll
    for (int mi = 0; mi < 4; mi++) {
        const int rl0 = wr * 64 + mi * 16 + l4;
        #pragma unroll
        for (int ni = 0; ni < 2; ni++) {
            const int cc = n0 + wc * 16 + ni * 8 + 2 * lm;
            #pragma unroll
            for (int h = 0; h < 2; h++) {
                const int rl = rl0 + h * 8;
                if (m0 + rl >= M) continue;
                const float w = s_wt[rl];
                float* o = Out + (size_t)s_tok[rl] * HD + cc;
                red_add2(o, w * acc[mi][ni][2 * h + 0], w * acc[mi][ni][2 * h + 1]);
            }
        }
    }
}

// ---------------- launch ----------------
extern "C" void kernel_launch(void* const* d_in, const int* in_sizes, int n_in,
                              void* d_out, int out_size) {
    const float* x       = (const float*)d_in[0];
    const float* gate_w  = (const float*)d_in[1];
    const float* gate_b  = (const float*)d_in[2];
    const float* w_gate  = (const float*)d_in[3];
    const float* w_up    = (const float*)d_in[4];
    const float* w_down  = (const float*)d_in[5];
    const float* sw_gate = (const float*)d_in[6];
    const float* sw_up   = (const float*)d_in[7];
    const float* sw_down = (const float*)d_in[8];
    float* out = (float*)d_out;

    __half *wg16, *wu16, *wd16, *sg16, *su16, *sd16, *xh, *hr, *hs;
    cudaGetSymbolAddress((void**)&wg16, w_g16);
    cudaGetSymbolAddress((void**)&wu16, w_u16);
    cudaGetSymbolAddress((void**)&wd16, w_d16);
    cudaGetSymbolAddress((void**)&sg16, sw_g16);
    cudaGetSymbolAddress((void**)&su16, sw_u16);
    cudaGetSymbolAddress((void**)&sd16, sw_d16);
    cudaGetSymbolAddress((void**)&xh,   x16);
    cudaGetSymbolAddress((void**)&hr,   h_r16);
    cudaGetSymbolAddress((void**)&hs,   h_s16);

    cudaFuncSetAttribute(gemm1_h, cudaFuncAttributeMaxDynamicSharedMemorySize, G1_SMEM);
    cudaFuncSetAttribute(gemm2_h, cudaFuncAttributeMaxDynamicSharedMemorySize, G2_SMEM);

    init_kernel<<<1, 32>>>();
    prologue<<<PRO_BLOCKS, 256>>>(
        x, gate_w, gate_b, (float4*)out,
        (const float4*)w_gate, (const float4*)w_up,
        (const float4*)sw_gate, (const float4*)sw_up, (const float4*)sw_down,
        (uint4*)wg16, (uint4*)wu16,
        (uint4*)sg16, (uint4*)su16, (uint4*)sd16, (uint4*)xh);

    // gate/up + silu: z 0..15 routed, z 16/17 shared halves, z 18.. wd-conv
    gemm1_h<<<dim3(22, NT / 256, NE + 2 + WD_ZSLICES), 512, G1_SMEM>>>(
        xh, wg16, wu16, sg16, su16, hr, hs,
        (const float4*)w_down, (uint4*)wd16);
    // down: z=0 shared (K=SID), z=1..16 routed (K=ID); v2 reductions
    gemm2_h<<<dim3(HD / 64, NT / 256, NE + 1), 512, G2_SMEM>>>(
        hr, wd16, hs, sd16, out);
}